// round 3
// baseline (speedup 1.0000x reference)
#include <cuda_runtime.h>
#include <cstdint>

#define TS 1460
#define NG 2000
#define NREC 24      // floats per (t,g) record: 18 softmax weights, prcp, temp, pet, gate bits, 2 pad
#define TCH 16       // timesteps per routing thread

// ---- scratch (static __device__ globals; no allocation at launch time) ----
__device__ float         g_pre [(size_t)TS * NG * NREC];   // ~280 MB
__device__ unsigned char g_gate[(size_t)TS * NG];
__device__ float         g_surf[(size_t)TS * NG];
__device__ float         g_base[(size_t)TS * NG];
__device__ float         g_uh  [2 * 15 * NG];

__constant__ float c_lo[32] = {0.f,0.5f,0.001f,0.3f,20.f,-8.f,1.f,0.1f,0.1f,1e-4f,1.f,1e-4f,0.1f,0.1f,50.f,-8.f,
                               1.f,-5.f,0.f,1.5f,0.f,0.01f,-1.f,0.f,0.f,0.f,50.f,50.f,0.3f,0.01f,0.5f,0.15f};
__constant__ float c_hi[32] = {1.f,3.f,3.f,1.f,300.f,-2.f,5.f,200.f,0.5f,0.9999f,50.f,0.9999f,50.f,100.f,500.f,-2.f,
                               5.f,2.f,5.f,3.f,5.f,0.2f,1.f,0.4f,1.f,1.f,500.f,500.f,20.f,5.f,13.f,1.5f};

__device__ __forceinline__ float sigm(float x) { return 1.f / (1.f + __expf(-x)); }
__device__ __forceinline__ float clip01(float x) { return fminf(fmaxf(x, 1e-6f), 1.f); }

// ============================================================================
// Kernel 1: per-(t,g) preprocess — softmax the 3 weight groups, gate bits,
// and repack {prcp,temp,pet} so the scan does 6 coalesced LDG.128 per step.
// ============================================================================
__global__ void prep_kernel(const float* __restrict__ xphy, const float* __restrict__ wts) {
    size_t i = (size_t)blockIdx.x * blockDim.x + threadIdx.x;
    if (i >= (size_t)TS * NG) return;
    const float4* wsrc = (const float4*)(wts + i * 24);
    float v[24];
#pragma unroll
    for (int k = 0; k < 6; k++) {
        float4 q = wsrc[k];
        v[4*k] = q.x; v[4*k+1] = q.y; v[4*k+2] = q.z; v[4*k+3] = q.w;
    }
    float out[24];
#pragma unroll
    for (int grp = 0; grp < 3; grp++) {
        float m = v[grp*6];
#pragma unroll
        for (int k = 1; k < 6; k++) m = fmaxf(m, v[grp*6 + k]);
        float e[6], s = 0.f;
#pragma unroll
        for (int k = 0; k < 6; k++) { e[k] = __expf(v[grp*6 + k] - m); s += e[k]; }
        float inv = 1.f / s;
#pragma unroll
        for (int k = 0; k < 6; k++) out[grp*6 + k] = e[k] * inv;
    }
    unsigned bits = 0;
#pragma unroll
    for (int k = 0; k < 6; k++) bits |= (v[18 + k] > 0.f) ? (1u << k) : 0u;  // round(sigmoid(w)) == (w>0)
    out[18] = xphy[i*3 + 0];
    out[19] = xphy[i*3 + 1];
    out[20] = xphy[i*3 + 2];
    out[21] = __uint_as_float(bits);
    out[22] = 0.f; out[23] = 0.f;
    float4* dst = (float4*)(g_pre + i * NREC);
#pragma unroll
    for (int k = 0; k < 6; k++) dst[k] = make_float4(out[4*k], out[4*k+1], out[4*k+2], out[4*k+3]);
    g_gate[i] = (unsigned char)bits;
}

// ============================================================================
// Kernel 2: per-cell unit-hydrograph weights (softmax of (a-1)ln k - k/b, k=1..15)
// ============================================================================
__global__ void uh_kernel(const float* __restrict__ hyb) {
    int g = blockIdx.x * blockDim.x + threadIdx.x;
    if (g >= NG) return;
    const float* h = hyb + (size_t)g * 32;
    float a1 = c_lo[28] + sigm(h[28]) * (c_hi[28] - c_lo[28]);
    float b1 = c_lo[29] + sigm(h[29]) * (c_hi[29] - c_lo[29]);
    float a2 = c_lo[30] + sigm(h[30]) * (c_hi[30] - c_lo[30]);
    float b2 = c_lo[31] + sigm(h[31]) * (c_hi[31] - c_lo[31]);
    float ib1 = 1.f / b1, ib2 = 1.f / b2;
    float lw1[15], lw2[15], m1 = -1e30f, m2 = -1e30f;
#pragma unroll
    for (int k = 0; k < 15; k++) {
        float kk = (float)(k + 1);
        float lk = __logf(kk);
        lw1[k] = (a1 - 1.f) * lk - kk * ib1;
        lw2[k] = (a2 - 1.f) * lk - kk * ib2;
        m1 = fmaxf(m1, lw1[k]); m2 = fmaxf(m2, lw2[k]);
    }
    float e1[15], e2[15], s1 = 0.f, s2 = 0.f;
#pragma unroll
    for (int k = 0; k < 15; k++) {
        e1[k] = __expf(lw1[k] - m1); s1 += e1[k];
        e2[k] = __expf(lw2[k] - m2); s2 += e2[k];
    }
    float i1 = 1.f / s1, i2 = 1.f / s2;
#pragma unroll
    for (int k = 0; k < 15; k++) {
        g_uh[k * NG + g]        = e1[k] * i1;
        g_uh[(15 + k) * NG + g] = e2[k] * i2;
    }
}

// ============================================================================
// Kernel 3: sequential scan over T. One thread per grid cell, one warp per SM
// (32-thread blocks) so each warp owns a full scheduler. Next-step record is
// prefetched at the top of the body to cover DRAM latency.
// ============================================================================
__global__ void __launch_bounds__(32, 1) scan_kernel(const float* __restrict__ hyb) {
    int g = blockIdx.x * 32 + threadIdx.x;
    if (g >= NG) return;
    const float* h = hyb + (size_t)g * 32;
    float P[32];
#pragma unroll
    for (int i = 0; i < 32; i++) P[i] = c_lo[i] + sigm(h[i]) * (c_hi[i] - c_lo[i]);

    // per-cell derived constants
    const float cc      = P[24] * (1.f - P[25]);
    const float Tbf = P[17], Kf = P[18], ddfmin = P[19], ddfplus = P[20];
    const float Kcum = P[21], Tbm = P[22], swi = P[23];
    const float msw1 = P[26];
    const float inv_m1 = 1.f / P[26], inv_m2 = 1.f / P[27];
    const float inf_pc = P[0], hbv_beta = P[1], vic_b = P[2], hm_a = P[3];
    const float perc_coef = P[10] / (1.f - P[11]);
    const float perc_sfc = P[11], crise = P[12];
    const float inv_x3a = 1.f / P[4];
    const float p10a = exp2f(P[5] * 3.3219280948873623f);   // 10^bfc1
    const float bfn1 = P[6], bfmax1 = P[7], lam = P[8];
    const float c_lam = bfmax1 / expm1f(lam);
    const float thresh = P[9];
    const float c_th = bfmax1 / (1.f - thresh);
    const float inv_x3b = 1.f / P[14];
    const float p10b = exp2f(P[15] * 3.3219280948873623f);  // 10^bfc2
    const float bfn2 = P[16], bfmax2 = P[13];

    float snow = 1e-6f, liq = 1e-6f, cum = 1e-6f, sw1 = 1e-6f, sw2 = 1e-6f;

    const float4* rec = (const float4*)g_pre;
    size_t r = ((size_t)0 * NG + g) * 6;
    float4 c0 = rec[r], c1 = rec[r+1], c2 = rec[r+2], c3 = rec[r+3], c4 = rec[r+4], c5 = rec[r+5];

    for (int t = 0; t < TS; t++) {
        // prefetch next record first (independent of this step's compute)
        int tn = (t + 1 < TS) ? (t + 1) : (TS - 1);
        size_t rn = ((size_t)tn * NG + g) * 6;
        float4 n0 = rec[rn], n1 = rec[rn+1], n2 = rec[rn+2], n3 = rec[rn+3], n4 = rec[rn+4], n5 = rec[rn+5];

        // unpack current record
        const float wi0 = c0.x, wi1 = c0.y, wi2 = c0.z, wi3 = c0.w, wi4 = c1.x, wi5 = c1.y;
        const float wa0 = c1.z, wa1 = c1.w, wa2 = c2.x, wa3 = c2.y, wa4 = c2.z, wa5 = c2.w;
        const float wb0 = c3.x, wb1 = c3.y, wb2 = c3.z, wb3 = c3.w, wb4 = c4.x, wb5 = c4.y;
        const float prcp = c4.z, temp = c4.w, pet = c5.x;
        const unsigned bits = __float_as_uint(c5.y);
        const float gb0 = (float)(bits & 1),        gb1 = (float)((bits >> 1) & 1);
        const float gb2 = (float)((bits >> 2) & 1), gb3 = (float)((bits >> 3) & 1);

        // --- snow module ---
        float rain  = (temp >= 0.f) ? prcp : 0.f;
        float snowf = (temp <  0.f) ? prcp : 0.f;
        float canopy = pet * cc;
        rain  = fmaxf(rain  - canopy * gb2, 0.f);
        snowf = fmaxf(snowf - canopy * gb3, 0.f);
        float refreeze = fminf(liq, Kf * fmaxf(Tbf - temp, 0.f));
        snow = snow + snowf + refreeze;
        liq  = liq - refreeze;
        float ddf  = ddfmin + ddfplus * (1.f - __expf(-Kcum * cum));
        float melt = fminf(snow, ddf * fmaxf(temp - Tbm, 0.f));
        snow -= melt;
        cum = (snow < 1e-6f) ? 1e-6f : (cum + melt);
        liq += melt;
        float overflow = fmaxf(liq - swi * snow, 0.f);
        liq -= overflow;
        float wavail = rain + overflow;

        // --- infiltration blend ---
        float sat1 = clip01(sw1 * inv_m1);
        float dry1 = clip01(1.f - sat1);
        float o1 = 1.f - __powf(sat1, hbv_beta);
        float o2 = __powf(dry1, vic_b);
        float fsum = wi0 * inf_pc + wi1 * o1 + wi2 * o2 + wi3 * (hm_a * dry1)
                   + wi4 * (1.f - sat1 * sat1) + wi5;
        float infil = wavail * fsum;
        sw1 += infil;
        float excess = fmaxf(sw1 - msw1, 0.f);
        sw1 -= excess;
        float surf = wavail - infil + excess;

        // --- percolation / capillary rise / ET ---
        sat1 = clip01(sw1 * inv_m1);
        float perc = gb0 * perc_coef * fmaxf(sat1 - perc_sfc, 0.f);
        perc = fminf(perc, sw1);
        sw1 -= perc; sw2 += perc;
        float sat2 = clip01(sw2 * inv_m2);
        sat1 = clip01(sw1 * inv_m1);
        float capi = fminf(gb1 * crise * (1.f - sat1) * sat2, sw2);
        sw2 -= capi; sw1 += capi;
        sat1 = clip01(sw1 * inv_m1);
        float et = fminf(pet * sat1, sw1);
        sw1 -= et;
        sat1 = clip01(sw1 * inv_m1);

        // --- baseflow 1 blend ---
        // (1 + r^4)^(-0.25) == sqrtf(rsqrtf(q)):  rsqrt(q)=q^-1/2, sqrt of that = q^-1/4
        float ra = sw1 * inv_x3a; float ra2 = ra * ra; float qa = 1.f + ra2 * ra2;
        float b0v = sw1 * (1.f - sqrtf(rsqrtf(qa)));
        float b1v = p10a * sw1;
        float b2v = bfmax1 * __powf(sat1, bfn1);
        float b3v = bfmax1 * sat1;
        float b4v = c_lam * expm1f(lam * sat1);
        float b5v = c_th * fmaxf(sat1 - thresh, 0.f);
        float bf1 = fminf(wa0*b0v + wa1*b1v + wa2*b2v + wa3*b3v + wa4*b4v + wa5*b5v, sw1);
        sw1 -= bf1;

        // --- baseflow 2 blend ---
        sat2 = clip01(sw2 * inv_m2);
        float rb = sw2 * inv_x3b; float rb2 = rb * rb; float qb = 1.f + rb2 * rb2;
        float d0 = sw2 * (1.f - sqrtf(rsqrtf(qb)));
        float d1 = p10b * sw2;
        float d2 = bfmax2 * __powf(sat2, bfn2);
        float d3 = bfmax2 * sat2;
        float d4 = bfmax2 * sat2 * sat2;
        float d5 = d1 * sat2;
        float bf2 = fminf(wb0*d0 + wb1*d1 + wb2*d2 + wb3*d3 + wb4*d4 + wb5*d5, sw2);
        sw2 -= bf2;

        g_surf[(size_t)t * NG + g] = surf;
        g_base[(size_t)t * NG + g] = bf1 + bf2;

        c0 = n0; c1 = n1; c2 = n2; c3 = n3; c4 = n4; c5 = n5;
    }
}

// ============================================================================
// Kernel 4: 15-tap UH routing + gating + final sum. Each thread: one cell,
// TCH timesteps, register-resident window. All loads/stores coalesced.
// ============================================================================
__global__ void __launch_bounds__(128) route_kernel(float* __restrict__ out) {
    int g  = blockIdx.x * 128 + threadIdx.x;
    int t0 = blockIdx.y * TCH;
    if (g >= NG) return;
    float u1[15], u2[15];
#pragma unroll
    for (int k = 0; k < 15; k++) {
        u1[k] = g_uh[k * NG + g];
        u2[k] = g_uh[(15 + k) * NG + g];
    }
    float s[TCH + 14], b[TCH + 14];
#pragma unroll
    for (int i = 0; i < TCH + 14; i++) {
        int tt = t0 - 14 + i;
        bool ok = (tt >= 0) && (tt < TS);
        s[i] = ok ? g_surf[(size_t)tt * NG + g] : 0.f;
        b[i] = ok ? g_base[(size_t)tt * NG + g] : 0.f;
    }
#pragma unroll
    for (int j = 0; j < TCH; j++) {
        int t = t0 + j;
        if (t < TS) {
            float cs = 0.f, cb = 0.f;
#pragma unroll
            for (int l = 0; l < 15; l++) {
                cs += u1[l] * s[14 + j - l];
                cb += u2[l] * b[14 + j - l];
            }
            unsigned bits = g_gate[(size_t)t * NG + g];
            float g4 = (float)((bits >> 4) & 1);
            float g5 = (float)((bits >> 5) & 1);
            out[(size_t)t * NG + g] = g4 * cs + (1.f - g4) * s[14 + j]
                                    + g5 * cb + (1.f - g5) * b[14 + j];
        }
    }
}

// ============================================================================
extern "C" void kernel_launch(void* const* d_in, const int* in_sizes, int n_in,
                              void* d_out, int out_size) {
    // Select inputs by element count (robust to metadata ordering):
    // x_phy = 1460*2000*3 = 8,760,000 ; weights = 1460*2000*24 = 70,080,000 ; hybrid = 2000*32 = 64,000
    const float* xphy = nullptr; const float* wts = nullptr; const float* hyb = nullptr;
    for (int i = 0; i < n_in; i++) {
        if (in_sizes[i] == TS * NG * 3)       xphy = (const float*)d_in[i];
        else if (in_sizes[i] == TS * NG * 24) wts  = (const float*)d_in[i];
        else if (in_sizes[i] == NG * 32)      hyb  = (const float*)d_in[i];
    }
    float* out = (float*)d_out;                  // (1460, 2000)

    size_t total = (size_t)TS * NG;
    prep_kernel<<<(unsigned)((total + 255) / 256), 256>>>(xphy, wts);
    uh_kernel<<<(NG + 127) / 128, 128>>>(hyb);
    scan_kernel<<<(NG + 31) / 32, 32>>>(hyb);
    dim3 rg((NG + 127) / 128, (TS + TCH - 1) / TCH);
    route_kernel<<<rg, 128>>>(out);
}

// round 4
// speedup vs baseline: 1.4826x; 1.4826x over previous
#include <cuda_runtime.h>
#include <cstdint>

#define TS 1460
#define NG 2000
#define NREC 24      // floats per (t,g) record
#define TCH 16       // timesteps per routing thread

// ---- scratch (static __device__ globals; no allocation at launch time) ----
__device__ float         g_pre [(size_t)TS * NG * NREC];   // ~280 MB
__device__ unsigned char g_gate[(size_t)TS * NG];
__device__ float         g_surf[(size_t)TS * NG];
__device__ float         g_base[(size_t)TS * NG];
__device__ float         g_uh  [2 * 15 * NG];

__constant__ float c_lo[32] = {0.f,0.5f,0.001f,0.3f,20.f,-8.f,1.f,0.1f,0.1f,1e-4f,1.f,1e-4f,0.1f,0.1f,50.f,-8.f,
                               1.f,-5.f,0.f,1.5f,0.f,0.01f,-1.f,0.f,0.f,0.f,50.f,50.f,0.3f,0.01f,0.5f,0.15f};
__constant__ float c_hi[32] = {1.f,3.f,3.f,1.f,300.f,-2.f,5.f,200.f,0.5f,0.9999f,50.f,0.9999f,50.f,100.f,500.f,-2.f,
                               5.f,2.f,5.f,3.f,5.f,0.2f,1.f,0.4f,1.f,1.f,500.f,500.f,20.f,5.f,13.f,1.5f};

__device__ __forceinline__ float sigm(float x) { return 1.f / (1.f + __expf(-x)); }
__device__ __forceinline__ float clip01(float x) { return fminf(fmaxf(x, 1e-6f), 1.f); }
__device__ __forceinline__ void prefetchL2(const void* p) {
    asm volatile("prefetch.global.L2 [%0];" :: "l"(p));
}

// ============================================================================
// Kernel 1: per-(t,g) preprocess — softmax the 3 weight groups, gate bits,
// and repack {prcp,temp,pet} so the scan does 6 coalesced LDG.128 per step.
// ============================================================================
__global__ void prep_kernel(const float* __restrict__ xphy, const float* __restrict__ wts) {
    size_t i = (size_t)blockIdx.x * blockDim.x + threadIdx.x;
    if (i >= (size_t)TS * NG) return;
    const float4* wsrc = (const float4*)(wts + i * 24);
    float v[24];
#pragma unroll
    for (int k = 0; k < 6; k++) {
        float4 q = wsrc[k];
        v[4*k] = q.x; v[4*k+1] = q.y; v[4*k+2] = q.z; v[4*k+3] = q.w;
    }
    float out[24];
#pragma unroll
    for (int grp = 0; grp < 3; grp++) {
        float m = v[grp*6];
#pragma unroll
        for (int k = 1; k < 6; k++) m = fmaxf(m, v[grp*6 + k]);
        float e[6], s = 0.f;
#pragma unroll
        for (int k = 0; k < 6; k++) { e[k] = __expf(v[grp*6 + k] - m); s += e[k]; }
        float inv = 1.f / s;
#pragma unroll
        for (int k = 0; k < 6; k++) out[grp*6 + k] = e[k] * inv;
    }
    unsigned bits = 0;
#pragma unroll
    for (int k = 0; k < 6; k++) bits |= (v[18 + k] > 0.f) ? (1u << k) : 0u;  // round(sigmoid(w)) == (w>0)
    out[18] = xphy[i*3 + 0];
    out[19] = xphy[i*3 + 1];
    out[20] = xphy[i*3 + 2];
    out[21] = __uint_as_float(bits);
    out[22] = 0.f; out[23] = 0.f;
    float4* dst = (float4*)(g_pre + i * NREC);
#pragma unroll
    for (int k = 0; k < 6; k++) dst[k] = make_float4(out[4*k], out[4*k+1], out[4*k+2], out[4*k+3]);
    g_gate[i] = (unsigned char)bits;
}

// ============================================================================
// Kernel 2: per-cell unit-hydrograph weights
// ============================================================================
__global__ void uh_kernel(const float* __restrict__ hyb) {
    int g = blockIdx.x * blockDim.x + threadIdx.x;
    if (g >= NG) return;
    const float* h = hyb + (size_t)g * 32;
    float a1 = c_lo[28] + sigm(h[28]) * (c_hi[28] - c_lo[28]);
    float b1 = c_lo[29] + sigm(h[29]) * (c_hi[29] - c_lo[29]);
    float a2 = c_lo[30] + sigm(h[30]) * (c_hi[30] - c_lo[30]);
    float b2 = c_lo[31] + sigm(h[31]) * (c_hi[31] - c_lo[31]);
    float ib1 = 1.f / b1, ib2 = 1.f / b2;
    float lw1[15], lw2[15], m1 = -1e30f, m2 = -1e30f;
#pragma unroll
    for (int k = 0; k < 15; k++) {
        float kk = (float)(k + 1);
        float lk = __logf(kk);
        lw1[k] = (a1 - 1.f) * lk - kk * ib1;
        lw2[k] = (a2 - 1.f) * lk - kk * ib2;
        m1 = fmaxf(m1, lw1[k]); m2 = fmaxf(m2, lw2[k]);
    }
    float e1[15], e2[15], s1 = 0.f, s2 = 0.f;
#pragma unroll
    for (int k = 0; k < 15; k++) {
        e1[k] = __expf(lw1[k] - m1); s1 += e1[k];
        e2[k] = __expf(lw2[k] - m2); s2 += e2[k];
    }
    float i1 = 1.f / s1, i2 = 1.f / s2;
#pragma unroll
    for (int k = 0; k < 15; k++) {
        g_uh[k * NG + g]        = e1[k] * i1;
        g_uh[(15 + k) * NG + g] = e2[k] * i2;
    }
}

// ============================================================================
// Kernel 3: sequential scan over T. One thread per cell, one warp per SM.
// Depth-2 register software pipeline + L2 prefetch 6 steps ahead: each
// record's LDGs get ~2 step bodies of cover and hit L2 (prefetched).
// ============================================================================
__global__ void __launch_bounds__(32, 1) scan_kernel(const float* __restrict__ hyb) {
    int g = blockIdx.x * 32 + threadIdx.x;
    if (g >= NG) return;
    const float* h = hyb + (size_t)g * 32;
    float P[32];
#pragma unroll
    for (int i = 0; i < 32; i++) P[i] = c_lo[i] + sigm(h[i]) * (c_hi[i] - c_lo[i]);

    // per-cell derived constants
    const float cc      = P[24] * (1.f - P[25]);
    const float Tbf = P[17], Kf = P[18], ddfmin = P[19], ddfplus = P[20];
    const float Kcum = P[21], Tbm = P[22], swi = P[23];
    const float msw1 = P[26];
    const float inv_m1 = 1.f / P[26], inv_m2 = 1.f / P[27];
    const float inf_pc = P[0], hbv_beta = P[1], vic_b = P[2], hm_a = P[3];
    const float perc_coef = P[10] / (1.f - P[11]);
    const float perc_sfc = P[11], crise = P[12];
    const float inv_x3a = 1.f / P[4];
    const float p10a = exp2f(P[5] * 3.3219280948873623f);   // 10^bfc1
    const float bfn1 = P[6], bfmax1 = P[7], lam = P[8];
    const float c_lam = bfmax1 / expm1f(lam);
    const float thresh = P[9];
    const float c_th = bfmax1 / (1.f - thresh);
    const float inv_x3b = 1.f / P[14];
    const float p10b = exp2f(P[15] * 3.3219280948873623f);  // 10^bfc2
    const float bfn2 = P[16], bfmax2 = P[13];

    float snow = 1e-6f, liq = 1e-6f, cum = 1e-6f, sw1 = 1e-6f, sw2 = 1e-6f;

    const float4* rec = (const float4*)g_pre;
    size_t r0 = ((size_t)0 * NG + g) * 6;
    size_t r1 = ((size_t)1 * NG + g) * 6;
    // depth-2 pipeline: c* = record[t], n* = record[t+1]
    float4 c0 = __ldcs(rec+r0),   c1 = __ldcs(rec+r0+1), c2 = __ldcs(rec+r0+2),
           c3 = __ldcs(rec+r0+3), c4 = __ldcs(rec+r0+4), c5 = __ldcs(rec+r0+5);
    float4 n0 = __ldcs(rec+r1),   n1 = __ldcs(rec+r1+1), n2 = __ldcs(rec+r1+2),
           n3 = __ldcs(rec+r1+3), n4 = __ldcs(rec+r1+4), n5 = __ldcs(rec+r1+5);
    // prime L2 for the first few steps
#pragma unroll
    for (int tp = 2; tp < 8; tp++) {
        const char* pp = (const char*)(rec + ((size_t)tp * NG + g) * 6);
        prefetchL2(pp); prefetchL2(pp + 64);
    }

    for (int t = 0; t < TS; t++) {
        // L2 prefetch 6+ steps ahead (no register cost)
        int tpf = t + 8; if (tpf >= TS) tpf = TS - 1;
        const char* pp = (const char*)(rec + ((size_t)tpf * NG + g) * 6);
        prefetchL2(pp); prefetchL2(pp + 64);

        // issue loads for t+2 (consumed two bodies later)
        int t2 = t + 2; if (t2 >= TS) t2 = TS - 1;
        size_t r2 = ((size_t)t2 * NG + g) * 6;
        float4 m0 = __ldcs(rec+r2),   m1v = __ldcs(rec+r2+1), m2v = __ldcs(rec+r2+2),
               m3 = __ldcs(rec+r2+3), m4 = __ldcs(rec+r2+4),  m5 = __ldcs(rec+r2+5);

        // unpack current record
        const float wi0 = c0.x, wi1 = c0.y, wi2 = c0.z, wi3 = c0.w, wi4 = c1.x, wi5 = c1.y;
        const float wa0 = c1.z, wa1 = c1.w, wa2 = c2.x, wa3 = c2.y, wa4 = c2.z, wa5 = c2.w;
        const float wb0 = c3.x, wb1 = c3.y, wb2 = c3.z, wb3 = c3.w, wb4 = c4.x, wb5 = c4.y;
        const float prcp = c4.z, temp = c4.w, pet = c5.x;
        const unsigned bits = __float_as_uint(c5.y);
        const float gb0 = (float)(bits & 1),        gb1 = (float)((bits >> 1) & 1);
        const float gb2 = (float)((bits >> 2) & 1), gb3 = (float)((bits >> 3) & 1);

        // --- snow module ---
        float rain  = (temp >= 0.f) ? prcp : 0.f;
        float snowf = (temp <  0.f) ? prcp : 0.f;
        float canopy = pet * cc;
        rain  = fmaxf(rain  - canopy * gb2, 0.f);
        snowf = fmaxf(snowf - canopy * gb3, 0.f);
        float refreeze = fminf(liq, Kf * fmaxf(Tbf - temp, 0.f));
        snow = snow + snowf + refreeze;
        liq  = liq - refreeze;
        float ddf  = ddfmin + ddfplus * (1.f - __expf(-Kcum * cum));
        float melt = fminf(snow, ddf * fmaxf(temp - Tbm, 0.f));
        snow -= melt;
        cum = (snow < 1e-6f) ? 1e-6f : (cum + melt);
        liq += melt;
        float overflow = fmaxf(liq - swi * snow, 0.f);
        liq -= overflow;
        float wavail = rain + overflow;

        // --- infiltration blend ---
        float sat1 = clip01(sw1 * inv_m1);
        float dry1 = clip01(1.f - sat1);
        float o1 = 1.f - __powf(sat1, hbv_beta);
        float o2 = __powf(dry1, vic_b);
        float fsum = wi0 * inf_pc + wi1 * o1 + wi2 * o2 + wi3 * (hm_a * dry1)
                   + wi4 * (1.f - sat1 * sat1) + wi5;
        float infil = wavail * fsum;
        sw1 += infil;
        float excess = fmaxf(sw1 - msw1, 0.f);
        sw1 -= excess;
        float surf = wavail - infil + excess;

        // --- percolation / capillary rise / ET ---
        sat1 = clip01(sw1 * inv_m1);
        float perc = gb0 * perc_coef * fmaxf(sat1 - perc_sfc, 0.f);
        perc = fminf(perc, sw1);
        sw1 -= perc; sw2 += perc;
        float sat2 = clip01(sw2 * inv_m2);
        sat1 = clip01(sw1 * inv_m1);
        float capi = fminf(gb1 * crise * (1.f - sat1) * sat2, sw2);
        sw2 -= capi; sw1 += capi;
        sat1 = clip01(sw1 * inv_m1);
        float et = fminf(pet * sat1, sw1);
        sw1 -= et;
        sat1 = clip01(sw1 * inv_m1);

        // --- baseflow 1 blend ---
        // (1 + r^4)^(-0.25) == sqrtf(rsqrtf(q))
        float ra = sw1 * inv_x3a; float ra2 = ra * ra; float qa = 1.f + ra2 * ra2;
        float b0v = sw1 * (1.f - sqrtf(rsqrtf(qa)));
        float b1v = p10a * sw1;
        float b2v = bfmax1 * __powf(sat1, bfn1);
        float b3v = bfmax1 * sat1;
        float b4v = c_lam * expm1f(lam * sat1);
        float b5v = c_th * fmaxf(sat1 - thresh, 0.f);
        float bf1 = fminf(wa0*b0v + wa1*b1v + wa2*b2v + wa3*b3v + wa4*b4v + wa5*b5v, sw1);
        sw1 -= bf1;

        // --- baseflow 2 blend ---
        sat2 = clip01(sw2 * inv_m2);
        float rb = sw2 * inv_x3b; float rb2 = rb * rb; float qb = 1.f + rb2 * rb2;
        float d0 = sw2 * (1.f - sqrtf(rsqrtf(qb)));
        float d1 = p10b * sw2;
        float d2 = bfmax2 * __powf(sat2, bfn2);
        float d3 = bfmax2 * sat2;
        float d4 = bfmax2 * sat2 * sat2;
        float d5 = d1 * sat2;
        float bf2 = fminf(wb0*d0 + wb1*d1 + wb2*d2 + wb3*d3 + wb4*d4 + wb5*d5, sw2);
        sw2 -= bf2;

        g_surf[(size_t)t * NG + g] = surf;
        g_base[(size_t)t * NG + g] = bf1 + bf2;

        // rotate pipeline
        c0 = n0; c1 = n1; c2 = n2; c3 = n3; c4 = n4; c5 = n5;
        n0 = m0; n1 = m1v; n2 = m2v; n3 = m3; n4 = m4; n5 = m5;
    }
}

// ============================================================================
// Kernel 4: 15-tap UH routing + gating + final sum.
// ============================================================================
__global__ void __launch_bounds__(128) route_kernel(float* __restrict__ out) {
    int g  = blockIdx.x * 128 + threadIdx.x;
    int t0 = blockIdx.y * TCH;
    if (g >= NG) return;
    float u1[15], u2[15];
#pragma unroll
    for (int k = 0; k < 15; k++) {
        u1[k] = g_uh[k * NG + g];
        u2[k] = g_uh[(15 + k) * NG + g];
    }
    float s[TCH + 14], b[TCH + 14];
#pragma unroll
    for (int i = 0; i < TCH + 14; i++) {
        int tt = t0 - 14 + i;
        bool ok = (tt >= 0) && (tt < TS);
        s[i] = ok ? g_surf[(size_t)tt * NG + g] : 0.f;
        b[i] = ok ? g_base[(size_t)tt * NG + g] : 0.f;
    }
#pragma unroll
    for (int j = 0; j < TCH; j++) {
        int t = t0 + j;
        if (t < TS) {
            float cs = 0.f, cb = 0.f;
#pragma unroll
            for (int l = 0; l < 15; l++) {
                cs += u1[l] * s[14 + j - l];
                cb += u2[l] * b[14 + j - l];
            }
            unsigned bits = g_gate[(size_t)t * NG + g];
            float g4 = (float)((bits >> 4) & 1);
            float g5 = (float)((bits >> 5) & 1);
            out[(size_t)t * NG + g] = g4 * cs + (1.f - g4) * s[14 + j]
                                    + g5 * cb + (1.f - g5) * b[14 + j];
        }
    }
}

// ============================================================================
extern "C" void kernel_launch(void* const* d_in, const int* in_sizes, int n_in,
                              void* d_out, int out_size) {
    const float* xphy = nullptr; const float* wts = nullptr; const float* hyb = nullptr;
    for (int i = 0; i < n_in; i++) {
        if (in_sizes[i] == TS * NG * 3)       xphy = (const float*)d_in[i];
        else if (in_sizes[i] == TS * NG * 24) wts  = (const float*)d_in[i];
        else if (in_sizes[i] == NG * 32)      hyb  = (const float*)d_in[i];
    }
    float* out = (float*)d_out;                  // (1460, 2000)

    size_t total = (size_t)TS * NG;
    prep_kernel<<<(unsigned)((total + 255) / 256), 256>>>(xphy, wts);
    uh_kernel<<<(NG + 127) / 128, 128>>>(hyb);
    scan_kernel<<<(NG + 31) / 32, 32>>>(hyb);
    dim3 rg((NG + 127) / 128, (TS + TCH - 1) / TCH);
    route_kernel<<<rg, 128>>>(out);
}